// round 10
// baseline (speedup 1.0000x reference)
#include <cuda_runtime.h>
#include <cuda_bf16.h>
#include <math.h>

#define BATCH 64
#define N100 100
#define N50  50
#define TLEN 100
#define KFC  512

#define FN_LOG        0
#define FN_REEIG      1
#define FN_EXPNEGHALF 2
#define FN_SQRT       3
#define FN_SQRT_BOTH  4

// ---------------------------------------------------------------------------
// Scratch
// ---------------------------------------------------------------------------
struct Scratch {
    float cov   [BATCH * N100 * N100];
    float bufA  [BATCH * N100 * N100];
    float bufA01[4 * BATCH * N100 * N100];
    float logmb [4 * BATCH * N100 * N100];
    float meanb [4 * N100 * N100];
    float gib   [4 * N100 * N100];
    float s     [BATCH * N100 * N100];
    float reeig [BATCH * N100 * N100];
    float s01   [4 * BATCH * N100 * N100];
    float bimA  [2 * BATCH * N50 * N50];
    float bimB  [2 * BATCH * N50 * N50];
    float As    [2 * BATCH * N50 * N50];
    float Ais   [2 * BATCH * N50 * N50];
    float Mmid  [2 * BATCH * N50 * N50];
    float Ssq   [2 * BATCH * N50 * N50];
    float st2   [2 * BATCH * N50 * N50];        // st2..st5 MUST stay adjacent
    float st3   [2 * BATCH * N50 * N50];
    float st4   [2 * BATCH * N50 * N50];
    float st5   [2 * BATCH * N50 * N50];
    float feat  [BATCH * 8 * N50 * N50];
    float clsPart[125 * BATCH * 100];
};
__device__ Scratch g_scratch;

// ---------------------------------------------------------------------------
// Covariance kernel
// ---------------------------------------------------------------------------
__global__ void cov_kernel(const float* __restrict__ x, const float* __restrict__ fcw,
                           const float* __restrict__ fcb, float* __restrict__ cov)
{
    const int T = TLEN, N = N100, K = KFC, KT = 32, LD = N100 + 1;
    extern __shared__ float sh[];
    float* fs = sh;
    float* xs = fs + T * LD;
    float* ws = xs + KT * LD;
    float* rm = ws + KT * LD;
    __shared__ float r1[256];

    const int tid = threadIdx.x;
    const int b = blockIdx.x;
    const float* xb = x + (size_t)b * K * T;

    float acc[40];
    { int c = 0; for (int idx = tid; idx < T * N; idx += 256) acc[c++] = fcb[idx % N]; }

    for (int k0 = 0; k0 < K; k0 += KT) {
        __syncthreads();
        for (int l = tid; l < KT * T; l += 256) {
            int kk = l / T, t = l % T;
            xs[kk * LD + t] = xb[(size_t)(k0 + kk) * T + t];
        }
        for (int l = tid; l < KT * N; l += 256) {
            int n = l / KT, kk = l % KT;
            ws[kk * LD + n] = fcw[(size_t)n * K + k0 + kk];
        }
        __syncthreads();
        int c = 0;
        for (int idx = tid; idx < T * N; idx += 256) {
            int t = idx / N, n = idx % N;
            float a = acc[c];
            #pragma unroll
            for (int kk = 0; kk < KT; ++kk) a += xs[kk * LD + t] * ws[kk * LD + n];
            acc[c++] = a;
        }
    }
    __syncthreads();
    { int c = 0; for (int idx = tid; idx < T * N; idx += 256) fs[(idx / N) * LD + idx % N] = acc[c++]; }
    __syncthreads();
    if (tid < T) {
        float ssum = 0.f;
        for (int n = 0; n < N; ++n) ssum += fs[tid * LD + n];
        rm[tid] = ssum * (1.0f / N);
    }
    __syncthreads();
    for (int idx = tid; idx < T * N; idx += 256) fs[(idx / N) * LD + idx % N] -= rm[idx / N];
    __syncthreads();
    float ssq = 0.f;
    for (int idx = tid; idx < T * N; idx += 256) {
        float v = fs[(idx / N) * LD + idx % N];
        ssq += v * v;
    }
    r1[tid] = ssq; __syncthreads();
    for (int st = 128; st > 0; st >>= 1) { if (tid < st) r1[tid] += r1[tid + st]; __syncthreads(); }
    const float lam = 1e-5f * (r1[0] * (1.0f / (T - 1)));

    float* dst = cov + (size_t)b * N * N;
    for (int idx = tid; idx < N * N; idx += 256) {
        int n = idx / N, m = idx % N;
        float a = 0.f;
        for (int t = 0; t < T; ++t) a += fs[t * LD + n] * fs[t * LD + m];
        a *= (1.0f / (T - 1));
        if (n == m) a += lam;
        dst[idx] = a;
    }
}

// ---------------------------------------------------------------------------
// bimap: Y[b,c] = sym( L * X[b, c%hi] * L^T ), dual-weight split on channel
// ---------------------------------------------------------------------------
template<int NI, int NO>
__global__ void bimap_kernel(const float* __restrict__ Lsrc, const float* __restrict__ Lsrc2,
                             int splitC, const float* __restrict__ Xsrc,
                             float* __restrict__ Y, int hi, int ho, int perMat)
{
    const int LDI = NI + 1;
    extern __shared__ float sh[];
    float* Xs = sh;                  // NI*LDI
    float* Ls = Xs + NI * LDI;       // NO*LDI
    float* Ts = Ls + NO * LDI;       // NO*LDI

    const int tid = threadIdx.x, bs = blockDim.x;
    const int mm = blockIdx.x;
    const int b = mm / ho, c = mm % ho;
    const float* X = Xsrc + ((size_t)b * hi + (c % hi)) * NI * NI;
    const float* L = perMat ? (Lsrc + ((size_t)b * ho + c) * NO * NI)
                            : (c < splitC ? Lsrc + (size_t)c * NO * NI
                                          : Lsrc2 + (size_t)(c - splitC) * NO * NI);

    for (int idx = tid; idx < NI * NI; idx += bs) Xs[(idx / NI) * LDI + idx % NI] = X[idx];
    for (int idx = tid; idx < NO * NI; idx += bs) Ls[(idx / NI) * LDI + idx % NI] = L[idx];
    __syncthreads();
    // T = L * X   (j tiled by 2)
    for (int idx = tid; idx < NO * (NI / 2); idx += bs) {
        int o = idx / (NI / 2), j = (idx % (NI / 2)) * 2;
        float a0 = 0.f, a1 = 0.f;
        for (int k = 0; k < NI; ++k) {
            float l = Ls[o * LDI + k];
            a0 += l * Xs[k * LDI + j];
            a1 += l * Xs[k * LDI + j + 1];
        }
        Ts[o * LDI + j] = a0; Ts[o * LDI + j + 1] = a1;
    }
    __syncthreads();
    // Z = T * L^T  (p tiled by 2), stored into Xs
    for (int idx = tid; idx < NO * (NO / 2); idx += bs) {
        int o = idx / (NO / 2), p = (idx % (NO / 2)) * 2;
        float a0 = 0.f, a1 = 0.f;
        for (int j = 0; j < NI; ++j) {
            float t = Ts[o * LDI + j];
            a0 += t * Ls[p * LDI + j];
            a1 += t * Ls[(p + 1) * LDI + j];
        }
        Xs[o * LDI + p] = a0; Xs[o * LDI + p + 1] = a1;
    }
    __syncthreads();
    float* dst = Y + (size_t)mm * NO * NO;
    for (int idx = tid; idx < NO * NO; idx += bs) {
        int o = idx / NO, p = idx % NO;
        dst[idx] = 0.5f * (Xs[o * LDI + p] + Xs[p * LDI + o]);
    }
}

// ---------------------------------------------------------------------------
// mean over batch
// ---------------------------------------------------------------------------
__global__ void mean_kernel(const float* __restrict__ in, float* __restrict__ out,
                            int B, int C, int n2)
{
    int c = blockIdx.y;
    for (int idx = blockIdx.x * blockDim.x + threadIdx.x; idx < n2; idx += gridDim.x * blockDim.x) {
        float a = 0.f;
        for (int b = 0; b < B; ++b) a += in[((size_t)b * C + c) * n2 + idx];
        out[(size_t)c * n2 + idx] = a * (1.0f / B);
    }
}

// ---------------------------------------------------------------------------
// One-sided Jacobi eigensolver for SPD matrices + spectral recombine (v2).
//   - cached column norms in smem (analytic update after each rotation):
//     only the cross dot product dpq is reduced per pair (1 chain, not 3).
//   - VEC=8 (N=100) / VEC=4 (N=50): 13 active lanes; columns zero-padded to
//     LDC = 13*VEC so a 16-lane xor reduction (4 shfls) is exact.
//   - rotation threshold 1e-10 (|dpq| > 1e-5 |gp||gq|), safely above the fp32
//     dot-product noise floor so convergence detection actually fires.
// FN_EXPNEGHALF shifts by sigma=||A||_F at load (input may be indefinite);
//   f = exp((sigma - mu)/2) where mu = shifted eigenvalue.
// Output offset mapping: ooff = (((m/CC)%BB)*OB + (m/(CC*BB))*SB + m%CC) * N*N
// ---------------------------------------------------------------------------
template<int N, int FN, int THREADS>
__global__ void eigh1s_kernel(const float* __restrict__ in, float* __restrict__ out1,
                              float* __restrict__ out2,
                              int CC, int BB, int OB, int SB)
{
    constexpr int VEC    = (N == 100) ? 8 : 4;
    constexpr int ALANES = (N + VEC - 1) / VEC;   // 13
    constexpr int LDC    = ALANES * VEC;          // 104 / 52 (padded, zeroed)
    constexpr int NP     = N / 2;
    constexpr int NWARP  = THREADS / 32;

    __shared__ __align__(16) float G[N * LDC];
    __shared__ float nrm[N];
    __shared__ float sc1[N], sc2[N];
    __shared__ float red[NWARP];
    __shared__ float s_sigma;
    __shared__ int s_flag;

    const int tid = threadIdx.x, lane = tid & 31, w = tid >> 5;
    const int m = blockIdx.x;
    const float* src = in + (size_t)m * N * N;

    // load + symmetrize (column-major, padded rows zeroed); Frobenius^2 for shift
    float fro = 0.f;
    for (int idx = tid; idx < N * LDC; idx += THREADS) {
        int j = idx / LDC, i = idx % LDC;
        float v = 0.f;
        if (i < N) {
            v = 0.5f * (src[i * N + j] + src[j * N + i]);
            if (FN == FN_EXPNEGHALF) fro += v * v;
        }
        G[idx] = v;
    }
    if (FN == FN_EXPNEGHALF) {
        #pragma unroll
        for (int o = 16; o > 0; o >>= 1) fro += __shfl_xor_sync(0xffffffffu, fro, o);
        if (lane == 0) red[w] = fro;
        __syncthreads();
        if (tid == 0) {
            float a = 0.f;
            for (int i = 0; i < NWARP; ++i) a += red[i];
            s_sigma = sqrtf(a);
        }
        __syncthreads();
        for (int k = tid; k < N; k += THREADS) G[k * LDC + k] += s_sigma;
    }
    if (tid == 0) s_flag = 1;
    __syncthreads();

    // initial column norms (warp per column, depth-4 reduction over lower 16)
    for (int k = w; k < N; k += NWARP) {
        float d = 0.f;
        if (lane < ALANES) {
            #pragma unroll
            for (int h = 0; h < VEC / 4; ++h) {
                float4 a = *(const float4*)&G[k * LDC + VEC * lane + 4 * h];
                d += a.x*a.x + a.y*a.y + a.z*a.z + a.w*a.w;
            }
        }
        #pragma unroll
        for (int o = 8; o > 0; o >>= 1) d += __shfl_xor_sync(0xffffffffu, d, o);
        if (lane == 0) nrm[k] = d;
    }
    __syncthreads();

    // sweeps
    for (int sweep = 0; sweep < 16; ++sweep) {
        if (s_flag == 0) break;
        __syncthreads();
        if (tid == 0) s_flag = 0;
        __syncthreads();
        for (int r = 0; r < N - 1; ++r) {
            for (int k = w; k < NP; k += NWARP) {
                int p, q;
                if (k == 0) { p = N - 1; q = r; }
                else {
                    p = r + k;           if (p >= N - 1) p -= (N - 1);
                    q = r + (N - 1) - k; if (q >= N - 1) q -= (N - 1);
                }
                const float dpp = nrm[p], dqq = nrm[q];
                float up[VEC], uq[VEC];
                #pragma unroll
                for (int v = 0; v < VEC; ++v) { up[v] = 0.f; uq[v] = 0.f; }
                const bool act = lane < ALANES;
                if (act) {
                    #pragma unroll
                    for (int h = 0; h < VEC / 4; ++h) {
                        float4 a = *(const float4*)&G[p * LDC + VEC * lane + 4 * h];
                        float4 b = *(const float4*)&G[q * LDC + VEC * lane + 4 * h];
                        up[4*h+0]=a.x; up[4*h+1]=a.y; up[4*h+2]=a.z; up[4*h+3]=a.w;
                        uq[4*h+0]=b.x; uq[4*h+1]=b.y; uq[4*h+2]=b.z; uq[4*h+3]=b.w;
                    }
                }
                float dpq = 0.f;
                #pragma unroll
                for (int v = 0; v < VEC; ++v) dpq += up[v] * uq[v];
                #pragma unroll
                for (int o = 8; o > 0; o >>= 1) dpq += __shfl_xor_sync(0xffffffffu, dpq, o);

                if (dpq * dpq > 1e-10f * dpp * dqq) {
                    if (lane == 0) s_flag = 1;
                    float tau = (dqq - dpp) / (2.f * dpq);
                    float t = copysignf(1.f, tau) / (fabsf(tau) + sqrtf(1.f + tau * tau));
                    float c = rsqrtf(1.f + t * t), s = t * c;
                    if (act) {
                        #pragma unroll
                        for (int h = 0; h < VEC / 4; ++h) {
                            float4 np, nq;
                            np.x = c*up[4*h+0]-s*uq[4*h+0]; np.y = c*up[4*h+1]-s*uq[4*h+1];
                            np.z = c*up[4*h+2]-s*uq[4*h+2]; np.w = c*up[4*h+3]-s*uq[4*h+3];
                            nq.x = s*up[4*h+0]+c*uq[4*h+0]; nq.y = s*up[4*h+1]+c*uq[4*h+1];
                            nq.z = s*up[4*h+2]+c*uq[4*h+2]; nq.w = s*up[4*h+3]+c*uq[4*h+3];
                            *(float4*)&G[p * LDC + VEC * lane + 4 * h] = np;
                            *(float4*)&G[q * LDC + VEC * lane + 4 * h] = nq;
                        }
                    }
                    if (lane == 0) {
                        float cs2 = 2.f * c * s * dpq;
                        float c2 = c * c, s2 = s * s;
                        nrm[p] = c2 * dpp + s2 * dqq - cs2;
                        nrm[q] = s2 * dpp + c2 * dqq + cs2;
                    }
                }
            }
            __syncthreads();
        }
    }
    __syncthreads();

    // eigenvalues = exact column norms; scales = f(lambda)/lambda^2
    for (int k = w; k < N; k += NWARP) {
        float d = 0.f;
        if (lane < ALANES) {
            #pragma unroll
            for (int h = 0; h < VEC / 4; ++h) {
                float4 a = *(const float4*)&G[k * LDC + VEC * lane + 4 * h];
                d += a.x*a.x + a.y*a.y + a.z*a.z + a.w*a.w;
            }
        }
        #pragma unroll
        for (int o = 8; o > 0; o >>= 1) d += __shfl_xor_sync(0xffffffffu, d, o);
        if (lane == 0) {
            d = fmaxf(d, 1e-38f);
            float lam = sqrtf(d);
            float f1, f2 = 0.f;
            if (FN == FN_LOG)             f1 = logf(fmaxf(lam, 1e-6f));
            else if (FN == FN_REEIG)      f1 = fmaxf(lam, 1e-4f);
            else if (FN == FN_EXPNEGHALF) f1 = expf(0.5f * (s_sigma - lam));
            else if (FN == FN_SQRT)       f1 = sqrtf(fmaxf(lam, 1e-6f));
            else {
                float wc = fmaxf(lam, 1e-6f);
                f1 = sqrtf(wc); f2 = rsqrtf(wc);
            }
            sc1[k] = f1 / d;
            sc2[k] = f2 / d;
        }
    }
    __syncthreads();

    // recombine: out = sum_k sc[k] * g_k g_k^T  (register-tiled)
    constexpr int TY = NWARP;
    constexpr int II = (N + TY - 1) / TY;
    constexpr int JJ = (N + 31) / 32;
    const int tx = lane, ty = w;

    float acc1[II][JJ], acc2[II][JJ];
    #pragma unroll
    for (int ii = 0; ii < II; ++ii)
        #pragma unroll
        for (int jj = 0; jj < JJ; ++jj) { acc1[ii][jj] = 0.f; acc2[ii][jj] = 0.f; }

    for (int k = 0; k < N; ++k) {
        float f1 = sc1[k];
        float f2 = (FN == FN_SQRT_BOTH) ? sc2[k] : 0.f;
        float vj[JJ];
        #pragma unroll
        for (int jj = 0; jj < JJ; ++jj) {
            int j = tx + 32 * jj;
            vj[jj] = (j < N) ? G[k * LDC + j] : 0.f;
        }
        #pragma unroll
        for (int ii = 0; ii < II; ++ii) {
            int i = ty + TY * ii;
            if (i < N) {
                float vi = G[k * LDC + i];
                #pragma unroll
                for (int jj = 0; jj < JJ; ++jj) {
                    float pr = vi * vj[jj];
                    acc1[ii][jj] += pr * f1;
                    if (FN == FN_SQRT_BOTH) acc2[ii][jj] += pr * f2;
                }
            }
        }
    }

    const size_t ooff = ((size_t)((m / CC) % BB) * OB + (size_t)(m / (CC * BB)) * SB
                         + (size_t)(m % CC)) * N * N;
    float* dst1 = out1 + ooff;
    #pragma unroll
    for (int ii = 0; ii < II; ++ii) {
        int i = ty + TY * ii;
        if (i < N) {
            #pragma unroll
            for (int jj = 0; jj < JJ; ++jj) {
                int j = tx + 32 * jj;
                if (j < N) {
                    dst1[i * N + j] = acc1[ii][jj];
                    if (FN == FN_SQRT_BOTH) out2[ooff + i * N + j] = acc2[ii][jj];
                }
            }
        }
    }
}

// ---------------------------------------------------------------------------
// Classifier
// ---------------------------------------------------------------------------
__global__ void cls_gemm_kernel(const float* __restrict__ feat, const float* __restrict__ W,
                                float* __restrict__ part)
{
    const int KTOT = 20000, JT = 8;
    __shared__ float Ls[JT * 64];
    __shared__ float Ws[JT * 112];
    const int tid = threadIdx.x;
    const int tx = tid % 16, ty = tid / 16;
    const int kper = KTOT / gridDim.x;
    const int jbase = blockIdx.x * kper;
    float acc[4][7];
    for (int u = 0; u < 4; ++u) for (int v = 0; v < 7; ++v) acc[u][v] = 0.f;

    for (int j0 = jbase; j0 < jbase + kper; j0 += JT) {
        __syncthreads();
        for (int l = tid; l < JT * 64; l += 256) {
            int bb = l / JT, jj = l % JT;
            Ls[jj * 64 + bb] = feat[(size_t)bb * KTOT + j0 + jj];
        }
        for (int l = tid; l < JT * 112; l += 256) {
            int mi = l / JT, jj = l % JT;
            Ws[jj * 112 + mi] = (mi < 100) ? W[(size_t)mi * KTOT + j0 + jj] : 0.f;
        }
        __syncthreads();
        #pragma unroll
        for (int jj = 0; jj < JT; ++jj) {
            #pragma unroll
            for (int u = 0; u < 4; ++u) {
                float lv = Ls[jj * 64 + ty + 16 * u];
                #pragma unroll
                for (int v = 0; v < 7; ++v) acc[u][v] += lv * Ws[jj * 112 + tx + 16 * v];
            }
        }
    }
    float* dst = part + (size_t)blockIdx.x * 64 * 100;
    for (int u = 0; u < 4; ++u)
        for (int v = 0; v < 7; ++v) {
            int mi = tx + 16 * v;
            if (mi < 100) dst[(ty + 16 * u) * 100 + mi] = acc[u][v];
        }
}

__global__ void cls_reduce_kernel(const float* __restrict__ part, const float* __restrict__ bias,
                                  float* __restrict__ out, int nsplit)
{
    int i = blockIdx.x * blockDim.x + threadIdx.x;
    if (i < 64 * 100) {
        float a = bias[i % 100];
        for (int s = 0; s < nsplit; ++s) a += part[(size_t)s * 64 * 100 + i];
        out[i] = a;
    }
}

// ---------------------------------------------------------------------------
// Host launcher
// ---------------------------------------------------------------------------
static inline int bim_smem(int ni, int no) { return (ni * (ni + 1) + 2 * no * (ni + 1)) * 4; }

extern "C" void kernel_launch(void* const* d_in, const int* in_sizes, int n_in,
                              void* d_out, int out_size)
{
    const float* x      = (const float*)d_in[0];
    const float* fc_w   = (const float*)d_in[1];
    const float* fc_b   = (const float*)d_in[2];
    const float* stem_w = (const float*)d_in[3];
    const float* pre0_w = (const float*)d_in[4];
    const float* pre1_w = (const float*)d_in[5];
    const float* wr0    = (const float*)d_in[6];
    const float* wr1    = (const float*)d_in[7];
    const float* wn2    = (const float*)d_in[8];
    const float* wn4    = (const float*)d_in[9];
    const float* wn7    = (const float*)d_in[10];
    const float* cls_w  = (const float*)d_in[11];
    const float* cls_b  = (const float*)d_in[12];
    float* out = (float*)d_out;

    Scratch* S = nullptr;
    cudaGetSymbolAddress((void**)&S, g_scratch);

    const int COV_SMEM = (N100 * 101 + 2 * 32 * 101 + N100) * 4;
    const int B100 = bim_smem(100, 100), B10050 = bim_smem(100, 50), B50 = bim_smem(50, 50);

    cudaFuncSetAttribute((const void*)cov_kernel, cudaFuncAttributeMaxDynamicSharedMemorySize, COV_SMEM);
    cudaFuncSetAttribute((const void*)bimap_kernel<100,100>, cudaFuncAttributeMaxDynamicSharedMemorySize, B100);
    cudaFuncSetAttribute((const void*)bimap_kernel<100,50>,  cudaFuncAttributeMaxDynamicSharedMemorySize, B10050);
    cudaFuncSetAttribute((const void*)bimap_kernel<50,50>,   cudaFuncAttributeMaxDynamicSharedMemorySize, B50);

    const int BIG = 1 << 20;

    // 1) covariance
    cov_kernel<<<BATCH, 256, COV_SMEM>>>(x, fc_w, fc_b, S->cov);

    // 2) stem bimap + batchnorm (C=1)
    bimap_kernel<100,100><<<BATCH, 512, B100>>>(stem_w, stem_w, BIG, S->cov, S->bufA, 1, 1, 0);
    eigh1s_kernel<100,FN_LOG,512><<<BATCH, 512>>>(S->bufA, S->logmb, nullptr, 1, BIG, 1, 0);
    mean_kernel<<<dim3(40, 1), 256>>>(S->logmb, S->meanb, BATCH, 1, 10000);
    eigh1s_kernel<100,FN_EXPNEGHALF,512><<<1, 512>>>(S->meanb, S->gib, nullptr, 1, BIG, 1, 0);
    bimap_kernel<100,100><<<BATCH, 512, B100>>>(S->gib, S->gib, BIG, S->bufA, S->s, 1, 1, 0);

    // 3) reeig(s), shared by both pre branches
    eigh1s_kernel<100,FN_REEIG,512><<<BATCH, 512>>>(S->s, S->reeig, nullptr, 1, BIG, 1, 0);

    // 4) merged pre0+pre1 chain: 4 channels [pre0c0, pre0c1, pre1c0, pre1c1]
    bimap_kernel<100,100><<<4*BATCH, 512, B100>>>(pre0_w, pre1_w, 2, S->reeig, S->bufA01, 1, 4, 0);
    eigh1s_kernel<100,FN_LOG,512><<<4*BATCH, 512>>>(S->bufA01, S->logmb, nullptr, 1, BIG, 1, 0);
    mean_kernel<<<dim3(40, 4), 256>>>(S->logmb, S->meanb, BATCH, 4, 10000);
    eigh1s_kernel<100,FN_EXPNEGHALF,512><<<4, 512>>>(S->meanb, S->gib, nullptr, 1, BIG, 1, 0);
    bimap_kernel<100,100><<<4*BATCH, 512, B100>>>(S->gib, S->gib, BIG, S->bufA01, S->s01, 4, 4, 0);

    // 5) reduce to 50x50: s0 = channels 0,1 of s01; s1 = channels 2,3
    bimap_kernel<100,50><<<2*BATCH, 512, B10050>>>(wr0, wr0, BIG, S->s01, S->bimA, 4, 2, 0);
    bimap_kernel<100,50><<<2*BATCH, 512, B10050>>>(wr1, wr1, BIG, S->s01 + 2 * N100 * N100, S->bimB, 4, 2, 0);

    // bary2: dst = sym( sqrt(A) * sqrt( sym(invsqrt(A)*Bm*invsqrt(A)) ) * sqrt(A) )
    auto bary2 = [&](const float* A, const float* Bm, float* dst) {
        eigh1s_kernel<50,FN_SQRT_BOTH,512><<<2*BATCH, 512>>>(A, S->As, S->Ais, 1, BIG, 1, 0);
        bimap_kernel<50,50><<<2*BATCH, 512, B50>>>(S->Ais, S->Ais, BIG, Bm, S->Mmid, 2, 2, 1);
        eigh1s_kernel<50,FN_SQRT,512><<<2*BATCH, 512>>>(S->Mmid, S->Ssq, nullptr, 1, BIG, 1, 0);
        bimap_kernel<50,50><<<2*BATCH, 512, B50>>>(S->As, S->As, BIG, S->Ssq, dst, 2, 2, 1);
    };

    // 6) states
    bary2(S->bimA, S->bimB, S->st2);
    bimap_kernel<50,50><<<2*BATCH, 512, B50>>>(wn2, wn2, BIG, S->st2, S->bimA, 2, 2, 0);
    bary2(S->bimA, S->st2, S->st3);
    bimap_kernel<50,50><<<2*BATCH, 512, B50>>>(wn4, wn4, BIG, S->st3, S->bimA, 2, 2, 0);
    bary2(S->bimA, S->st2, S->st4);
    bimap_kernel<50,50><<<2*BATCH, 512, B50>>>(wn7, wn7, BIG, S->st3, S->bimB, 2, 2, 0);
    bary2(S->st4, S->bimB, S->st5);

    // 7) merged logm of st2..st5 (contiguous) into feat (B, 8, 50, 50)
    //    m = stage*128 + b*2 + c  ->  ooff = (b*8 + stage*2 + c) * 2500
    eigh1s_kernel<50,FN_LOG,512><<<8*BATCH, 512>>>(S->st2, S->feat, nullptr, 2, BATCH, 8, 2);

    // 8) classifier
    cls_gemm_kernel<<<125, 256>>>(S->feat, cls_w, S->clsPart);
    cls_reduce_kernel<<<25, 256>>>(S->clsPart, cls_b, out, 125);
}

// round 14
// speedup vs baseline: 1.1571x; 1.1571x over previous
#include <cuda_runtime.h>
#include <cuda_bf16.h>
#include <math.h>

#define BATCH 64
#define N100 100
#define N50  50
#define TLEN 100
#define KFC  512

#define FN_LOG        0
#define FN_REEIG      1
#define FN_EXPNEGHALF 2
#define FN_SQRT       3
#define FN_SQRT_BOTH  4

// ---------------------------------------------------------------------------
// Scratch
// ---------------------------------------------------------------------------
struct Scratch {
    float cov   [BATCH * N100 * N100];
    float bufA  [BATCH * N100 * N100];
    float bufA01[4 * BATCH * N100 * N100];
    float logmb [4 * BATCH * N100 * N100];
    float meanb [4 * N100 * N100];
    float gib   [4 * N100 * N100];
    float s     [BATCH * N100 * N100];
    float reeig [BATCH * N100 * N100];
    float s01   [4 * BATCH * N100 * N100];
    float bimA  [2 * BATCH * N50 * N50];
    float bimB  [2 * BATCH * N50 * N50];
    float As    [2 * BATCH * N50 * N50];
    float Ais   [2 * BATCH * N50 * N50];
    float Mmid  [2 * BATCH * N50 * N50];
    float Ssq   [2 * BATCH * N50 * N50];
    float st2   [2 * BATCH * N50 * N50];        // st2..st5 MUST stay adjacent
    float st3   [2 * BATCH * N50 * N50];
    float st4   [2 * BATCH * N50 * N50];
    float st5   [2 * BATCH * N50 * N50];
    float feat  [BATCH * 8 * N50 * N50];
    float clsPart[125 * BATCH * 100];
};
__device__ Scratch g_scratch;

// ---------------------------------------------------------------------------
// Covariance kernel
// ---------------------------------------------------------------------------
__global__ void cov_kernel(const float* __restrict__ x, const float* __restrict__ fcw,
                           const float* __restrict__ fcb, float* __restrict__ cov)
{
    const int T = TLEN, N = N100, K = KFC, KT = 32, LD = N100 + 1;
    extern __shared__ float sh[];
    float* fs = sh;
    float* xs = fs + T * LD;
    float* ws = xs + KT * LD;
    float* rm = ws + KT * LD;
    __shared__ float r1[256];

    const int tid = threadIdx.x;
    const int b = blockIdx.x;
    const float* xb = x + (size_t)b * K * T;

    float acc[40];
    { int c = 0; for (int idx = tid; idx < T * N; idx += 256) acc[c++] = fcb[idx % N]; }

    for (int k0 = 0; k0 < K; k0 += KT) {
        __syncthreads();
        for (int l = tid; l < KT * T; l += 256) {
            int kk = l / T, t = l % T;
            xs[kk * LD + t] = xb[(size_t)(k0 + kk) * T + t];
        }
        for (int l = tid; l < KT * N; l += 256) {
            int n = l / KT, kk = l % KT;
            ws[kk * LD + n] = fcw[(size_t)n * K + k0 + kk];
        }
        __syncthreads();
        int c = 0;
        for (int idx = tid; idx < T * N; idx += 256) {
            int t = idx / N, n = idx % N;
            float a = acc[c];
            #pragma unroll
            for (int kk = 0; kk < KT; ++kk) a += xs[kk * LD + t] * ws[kk * LD + n];
            acc[c++] = a;
        }
    }
    __syncthreads();
    { int c = 0; for (int idx = tid; idx < T * N; idx += 256) fs[(idx / N) * LD + idx % N] = acc[c++]; }
    __syncthreads();
    if (tid < T) {
        float ssum = 0.f;
        for (int n = 0; n < N; ++n) ssum += fs[tid * LD + n];
        rm[tid] = ssum * (1.0f / N);
    }
    __syncthreads();
    for (int idx = tid; idx < T * N; idx += 256) fs[(idx / N) * LD + idx % N] -= rm[idx / N];
    __syncthreads();
    float ssq = 0.f;
    for (int idx = tid; idx < T * N; idx += 256) {
        float v = fs[(idx / N) * LD + idx % N];
        ssq += v * v;
    }
    r1[tid] = ssq; __syncthreads();
    for (int st = 128; st > 0; st >>= 1) { if (tid < st) r1[tid] += r1[tid + st]; __syncthreads(); }
    const float lam = 1e-5f * (r1[0] * (1.0f / (T - 1)));

    float* dst = cov + (size_t)b * N * N;
    for (int idx = tid; idx < N * N; idx += 256) {
        int n = idx / N, m = idx % N;
        float a = 0.f;
        for (int t = 0; t < T; ++t) a += fs[t * LD + n] * fs[t * LD + m];
        a *= (1.0f / (T - 1));
        if (n == m) a += lam;
        dst[idx] = a;
    }
}

// ---------------------------------------------------------------------------
// bimap: Y[b,c] = sym( L * X[b, c%hi] * L^T ), dual-weight split on channel
// ---------------------------------------------------------------------------
template<int NI, int NO>
__global__ void bimap_kernel(const float* __restrict__ Lsrc, const float* __restrict__ Lsrc2,
                             int splitC, const float* __restrict__ Xsrc,
                             float* __restrict__ Y, int hi, int ho, int perMat)
{
    const int LDI = NI + 1;
    extern __shared__ float sh[];
    float* Xs = sh;                  // NI*LDI
    float* Ls = Xs + NI * LDI;       // NO*LDI
    float* Ts = Ls + NO * LDI;       // NO*LDI

    const int tid = threadIdx.x, bs = blockDim.x;
    const int mm = blockIdx.x;
    const int b = mm / ho, c = mm % ho;
    const float* X = Xsrc + ((size_t)b * hi + (c % hi)) * NI * NI;
    const float* L = perMat ? (Lsrc + ((size_t)b * ho + c) * NO * NI)
                            : (c < splitC ? Lsrc + (size_t)c * NO * NI
                                          : Lsrc2 + (size_t)(c - splitC) * NO * NI);

    for (int idx = tid; idx < NI * NI; idx += bs) Xs[(idx / NI) * LDI + idx % NI] = X[idx];
    for (int idx = tid; idx < NO * NI; idx += bs) Ls[(idx / NI) * LDI + idx % NI] = L[idx];
    __syncthreads();
    // T = L * X   (j tiled by 2)
    for (int idx = tid; idx < NO * (NI / 2); idx += bs) {
        int o = idx / (NI / 2), j = (idx % (NI / 2)) * 2;
        float a0 = 0.f, a1 = 0.f;
        for (int k = 0; k < NI; ++k) {
            float l = Ls[o * LDI + k];
            a0 += l * Xs[k * LDI + j];
            a1 += l * Xs[k * LDI + j + 1];
        }
        Ts[o * LDI + j] = a0; Ts[o * LDI + j + 1] = a1;
    }
    __syncthreads();
    // Z = T * L^T  (p tiled by 2), stored into Xs
    for (int idx = tid; idx < NO * (NO / 2); idx += bs) {
        int o = idx / (NO / 2), p = (idx % (NO / 2)) * 2;
        float a0 = 0.f, a1 = 0.f;
        for (int j = 0; j < NI; ++j) {
            float t = Ts[o * LDI + j];
            a0 += t * Ls[p * LDI + j];
            a1 += t * Ls[(p + 1) * LDI + j];
        }
        Xs[o * LDI + p] = a0; Xs[o * LDI + p + 1] = a1;
    }
    __syncthreads();
    float* dst = Y + (size_t)mm * NO * NO;
    for (int idx = tid; idx < NO * NO; idx += bs) {
        int o = idx / NO, p = idx % NO;
        dst[idx] = 0.5f * (Xs[o * LDI + p] + Xs[p * LDI + o]);
    }
}

// ---------------------------------------------------------------------------
// mean over batch
// ---------------------------------------------------------------------------
__global__ void mean_kernel(const float* __restrict__ in, float* __restrict__ out,
                            int B, int C, int n2)
{
    int c = blockIdx.y;
    for (int idx = blockIdx.x * blockDim.x + threadIdx.x; idx < n2; idx += gridDim.x * blockDim.x) {
        float a = 0.f;
        for (int b = 0; b < B; ++b) a += in[((size_t)b * C + c) * n2 + idx];
        out[(size_t)c * n2 + idx] = a * (1.0f / B);
    }
}

// ---------------------------------------------------------------------------
// One-sided Jacobi eigensolver (v3): R7's measured-good VEC=4/2 25-lane
// layout + cached column norms (1 reduction/pair, 5 shfls) + noise-safe
// threshold 1e-10 with 16-sweep cap.
// FN_EXPNEGHALF shifts by sigma=||A||_F at load (input may be indefinite);
//   f = exp((sigma - mu)/2).
// Output offset: ooff = (((m/CC)%BB)*OB + (m/(CC*BB))*SB + m%CC) * N*N
// ---------------------------------------------------------------------------
template<int N, int FN, int THREADS>
__global__ void eigh1s_kernel(const float* __restrict__ in, float* __restrict__ out1,
                              float* __restrict__ out2,
                              int CC, int BB, int OB, int SB)
{
    constexpr int VEC    = (N == 100) ? 4 : 2;
    constexpr int ALANES = N / VEC;               // 25
    constexpr int LDC    = N;                     // column stride (float4/2-aligned)
    constexpr int NP     = N / 2;
    constexpr int NWARP  = THREADS / 32;

    __shared__ __align__(16) float G[N * LDC];
    __shared__ float nrm[N];
    __shared__ float sc1[N], sc2[N];
    __shared__ float red[NWARP];
    __shared__ float s_sigma;
    __shared__ int s_flag;

    const int tid = threadIdx.x, lane = tid & 31, w = tid >> 5;
    const int m = blockIdx.x;
    const float* src = in + (size_t)m * N * N;

    // load + symmetrize (column-major); Frobenius^2 for shift
    float fro = 0.f;
    for (int idx = tid; idx < N * N; idx += THREADS) {
        int i = idx / N, j = idx % N;
        float v = 0.5f * (src[i * N + j] + src[j * N + i]);
        G[j * LDC + i] = v;
        if (FN == FN_EXPNEGHALF) fro += v * v;
    }
    if (FN == FN_EXPNEGHALF) {
        #pragma unroll
        for (int o = 16; o > 0; o >>= 1) fro += __shfl_xor_sync(0xffffffffu, fro, o);
        if (lane == 0) red[w] = fro;
        __syncthreads();
        if (tid == 0) {
            float a = 0.f;
            for (int i = 0; i < NWARP; ++i) a += red[i];
            s_sigma = sqrtf(a);
        }
        __syncthreads();
        for (int k = tid; k < N; k += THREADS) G[k * LDC + k] += s_sigma;
    }
    if (tid == 0) s_flag = 1;
    __syncthreads();

    // initial column norms
    for (int k = w; k < N; k += NWARP) {
        float d = 0.f;
        if (lane < ALANES) {
            if constexpr (VEC == 4) {
                float4 a = *(const float4*)&G[k * LDC + 4 * lane];
                d = a.x*a.x + a.y*a.y + a.z*a.z + a.w*a.w;
            } else {
                float2 a = *(const float2*)&G[k * LDC + 2 * lane];
                d = a.x*a.x + a.y*a.y;
            }
        }
        #pragma unroll
        for (int o = 16; o > 0; o >>= 1) d += __shfl_xor_sync(0xffffffffu, d, o);
        if (lane == 0) nrm[k] = d;
    }
    __syncthreads();

    // sweeps
    for (int sweep = 0; sweep < 16; ++sweep) {
        if (s_flag == 0) break;
        __syncthreads();
        if (tid == 0) s_flag = 0;
        __syncthreads();
        for (int r = 0; r < N - 1; ++r) {
            for (int k = w; k < NP; k += NWARP) {
                int p, q;
                if (k == 0) { p = N - 1; q = r; }
                else {
                    p = r + k;           if (p >= N - 1) p -= (N - 1);
                    q = r + (N - 1) - k; if (q >= N - 1) q -= (N - 1);
                }
                const float dpp = nrm[p], dqq = nrm[q];
                float up[VEC], uq[VEC];
                #pragma unroll
                for (int v = 0; v < VEC; ++v) { up[v] = 0.f; uq[v] = 0.f; }
                const bool act = lane < ALANES;
                if (act) {
                    if constexpr (VEC == 4) {
                        float4 a = *(const float4*)&G[p * LDC + 4 * lane];
                        float4 b = *(const float4*)&G[q * LDC + 4 * lane];
                        up[0]=a.x; up[1]=a.y; up[2]=a.z; up[3]=a.w;
                        uq[0]=b.x; uq[1]=b.y; uq[2]=b.z; uq[3]=b.w;
                    } else {
                        float2 a = *(const float2*)&G[p * LDC + 2 * lane];
                        float2 b = *(const float2*)&G[q * LDC + 2 * lane];
                        up[0]=a.x; up[1]=a.y;
                        uq[0]=b.x; uq[1]=b.y;
                    }
                }
                float dpq = 0.f;
                #pragma unroll
                for (int v = 0; v < VEC; ++v) dpq += up[v] * uq[v];
                #pragma unroll
                for (int o = 16; o > 0; o >>= 1) dpq += __shfl_xor_sync(0xffffffffu, dpq, o);

                if (dpq * dpq > 1e-10f * dpp * dqq) {
                    if (lane == 0) s_flag = 1;
                    float tau = (dqq - dpp) / (2.f * dpq);
                    float t = copysignf(1.f, tau) / (fabsf(tau) + sqrtf(1.f + tau * tau));
                    float c = rsqrtf(1.f + t * t), s = t * c;
                    if (act) {
                        if constexpr (VEC == 4) {
                            float4 np, nq;
                            np.x = c*up[0]-s*uq[0]; np.y = c*up[1]-s*uq[1];
                            np.z = c*up[2]-s*uq[2]; np.w = c*up[3]-s*uq[3];
                            nq.x = s*up[0]+c*uq[0]; nq.y = s*up[1]+c*uq[1];
                            nq.z = s*up[2]+c*uq[2]; nq.w = s*up[3]+c*uq[3];
                            *(float4*)&G[p * LDC + 4 * lane] = np;
                            *(float4*)&G[q * LDC + 4 * lane] = nq;
                        } else {
                            float2 np, nq;
                            np.x = c*up[0]-s*uq[0]; np.y = c*up[1]-s*uq[1];
                            nq.x = s*up[0]+c*uq[0]; nq.y = s*up[1]+c*uq[1];
                            *(float2*)&G[p * LDC + 2 * lane] = np;
                            *(float2*)&G[q * LDC + 2 * lane] = nq;
                        }
                    }
                    if (lane == 0) {
                        float cs2 = 2.f * c * s * dpq;
                        float c2 = c * c, s2 = s * s;
                        nrm[p] = c2 * dpp + s2 * dqq - cs2;
                        nrm[q] = s2 * dpp + c2 * dqq + cs2;
                    }
                }
            }
            __syncthreads();
        }
    }
    __syncthreads();

    // eigenvalues = exact column norms; scales = f(lambda)/lambda^2
    for (int k = w; k < N; k += NWARP) {
        float d = 0.f;
        if (lane < ALANES) {
            if constexpr (VEC == 4) {
                float4 a = *(const float4*)&G[k * LDC + 4 * lane];
                d = a.x*a.x + a.y*a.y + a.z*a.z + a.w*a.w;
            } else {
                float2 a = *(const float2*)&G[k * LDC + 2 * lane];
                d = a.x*a.x + a.y*a.y;
            }
        }
        #pragma unroll
        for (int o = 16; o > 0; o >>= 1) d += __shfl_xor_sync(0xffffffffu, d, o);
        if (lane == 0) {
            d = fmaxf(d, 1e-38f);
            float lam = sqrtf(d);
            float f1, f2 = 0.f;
            if (FN == FN_LOG)             f1 = logf(fmaxf(lam, 1e-6f));
            else if (FN == FN_REEIG)      f1 = fmaxf(lam, 1e-4f);
            else if (FN == FN_EXPNEGHALF) f1 = expf(0.5f * (s_sigma - lam));
            else if (FN == FN_SQRT)       f1 = sqrtf(fmaxf(lam, 1e-6f));
            else {
                float wc = fmaxf(lam, 1e-6f);
                f1 = sqrtf(wc); f2 = rsqrtf(wc);
            }
            sc1[k] = f1 / d;
            sc2[k] = f2 / d;
        }
    }
    __syncthreads();

    // recombine: out = sum_k sc[k] * g_k g_k^T  (register-tiled)
    constexpr int TY = NWARP;
    constexpr int II = (N + TY - 1) / TY;
    constexpr int JJ = (N + 31) / 32;
    const int tx = lane, ty = w;

    float acc1[II][JJ], acc2[II][JJ];
    #pragma unroll
    for (int ii = 0; ii < II; ++ii)
        #pragma unroll
        for (int jj = 0; jj < JJ; ++jj) { acc1[ii][jj] = 0.f; acc2[ii][jj] = 0.f; }

    for (int k = 0; k < N; ++k) {
        float f1 = sc1[k];
        float f2 = (FN == FN_SQRT_BOTH) ? sc2[k] : 0.f;
        float vj[JJ];
        #pragma unroll
        for (int jj = 0; jj < JJ; ++jj) {
            int j = tx + 32 * jj;
            vj[jj] = (j < N) ? G[k * LDC + j] : 0.f;
        }
        #pragma unroll
        for (int ii = 0; ii < II; ++ii) {
            int i = ty + TY * ii;
            if (i < N) {
                float vi = G[k * LDC + i];
                #pragma unroll
                for (int jj = 0; jj < JJ; ++jj) {
                    float pr = vi * vj[jj];
                    acc1[ii][jj] += pr * f1;
                    if (FN == FN_SQRT_BOTH) acc2[ii][jj] += pr * f2;
                }
            }
        }
    }

    const size_t ooff = ((size_t)((m / CC) % BB) * OB + (size_t)(m / (CC * BB)) * SB
                         + (size_t)(m % CC)) * N * N;
    float* dst1 = out1 + ooff;
    #pragma unroll
    for (int ii = 0; ii < II; ++ii) {
        int i = ty + TY * ii;
        if (i < N) {
            #pragma unroll
            for (int jj = 0; jj < JJ; ++jj) {
                int j = tx + 32 * jj;
                if (j < N) {
                    dst1[i * N + j] = acc1[ii][jj];
                    if (FN == FN_SQRT_BOTH) out2[ooff + i * N + j] = acc2[ii][jj];
                }
            }
        }
    }
}

// ---------------------------------------------------------------------------
// Classifier
// ---------------------------------------------------------------------------
__global__ void cls_gemm_kernel(const float* __restrict__ feat, const float* __restrict__ W,
                                float* __restrict__ part)
{
    const int KTOT = 20000, JT = 8;
    __shared__ float Ls[JT * 64];
    __shared__ float Ws[JT * 112];
    const int tid = threadIdx.x;
    const int tx = tid % 16, ty = tid / 16;
    const int kper = KTOT / gridDim.x;
    const int jbase = blockIdx.x * kper;
    float acc[4][7];
    for (int u = 0; u < 4; ++u) for (int v = 0; v < 7; ++v) acc[u][v] = 0.f;

    for (int j0 = jbase; j0 < jbase + kper; j0 += JT) {
        __syncthreads();
        for (int l = tid; l < JT * 64; l += 256) {
            int bb = l / JT, jj = l % JT;
            Ls[jj * 64 + bb] = feat[(size_t)bb * KTOT + j0 + jj];
        }
        for (int l = tid; l < JT * 112; l += 256) {
            int mi = l / JT, jj = l % JT;
            Ws[jj * 112 + mi] = (mi < 100) ? W[(size_t)mi * KTOT + j0 + jj] : 0.f;
        }
        __syncthreads();
        #pragma unroll
        for (int jj = 0; jj < JT; ++jj) {
            #pragma unroll
            for (int u = 0; u < 4; ++u) {
                float lv = Ls[jj * 64 + ty + 16 * u];
                #pragma unroll
                for (int v = 0; v < 7; ++v) acc[u][v] += lv * Ws[jj * 112 + tx + 16 * v];
            }
        }
    }
    float* dst = part + (size_t)blockIdx.x * 64 * 100;
    for (int u = 0; u < 4; ++u)
        for (int v = 0; v < 7; ++v) {
            int mi = tx + 16 * v;
            if (mi < 100) dst[(ty + 16 * u) * 100 + mi] = acc[u][v];
        }
}

__global__ void cls_reduce_kernel(const float* __restrict__ part, const float* __restrict__ bias,
                                  float* __restrict__ out, int nsplit)
{
    int i = blockIdx.x * blockDim.x + threadIdx.x;
    if (i < 64 * 100) {
        float a = bias[i % 100];
        for (int s = 0; s < nsplit; ++s) a += part[(size_t)s * 64 * 100 + i];
        out[i] = a;
    }
}

// ---------------------------------------------------------------------------
// Host launcher
// ---------------------------------------------------------------------------
static inline int bim_smem(int ni, int no) { return (ni * (ni + 1) + 2 * no * (ni + 1)) * 4; }

extern "C" void kernel_launch(void* const* d_in, const int* in_sizes, int n_in,
                              void* d_out, int out_size)
{
    const float* x      = (const float*)d_in[0];
    const float* fc_w   = (const float*)d_in[1];
    const float* fc_b   = (const float*)d_in[2];
    const float* stem_w = (const float*)d_in[3];
    const float* pre0_w = (const float*)d_in[4];
    const float* pre1_w = (const float*)d_in[5];
    const float* wr0    = (const float*)d_in[6];
    const float* wr1    = (const float*)d_in[7];
    const float* wn2    = (const float*)d_in[8];
    const float* wn4    = (const float*)d_in[9];
    const float* wn7    = (const float*)d_in[10];
    const float* cls_w  = (const float*)d_in[11];
    const float* cls_b  = (const float*)d_in[12];
    float* out = (float*)d_out;

    Scratch* S = nullptr;
    cudaGetSymbolAddress((void**)&S, g_scratch);

    const int COV_SMEM = (N100 * 101 + 2 * 32 * 101 + N100) * 4;
    const int B100 = bim_smem(100, 100), B10050 = bim_smem(100, 50), B50 = bim_smem(50, 50);

    cudaFuncSetAttribute((const void*)cov_kernel, cudaFuncAttributeMaxDynamicSharedMemorySize, COV_SMEM);
    cudaFuncSetAttribute((const void*)bimap_kernel<100,100>, cudaFuncAttributeMaxDynamicSharedMemorySize, B100);
    cudaFuncSetAttribute((const void*)bimap_kernel<100,50>,  cudaFuncAttributeMaxDynamicSharedMemorySize, B10050);
    cudaFuncSetAttribute((const void*)bimap_kernel<50,50>,   cudaFuncAttributeMaxDynamicSharedMemorySize, B50);

    const int BIG = 1 << 20;

    // 1) covariance
    cov_kernel<<<BATCH, 256, COV_SMEM>>>(x, fc_w, fc_b, S->cov);

    // 2) stem bimap + batchnorm (C=1)
    bimap_kernel<100,100><<<BATCH, 512, B100>>>(stem_w, stem_w, BIG, S->cov, S->bufA, 1, 1, 0);
    eigh1s_kernel<100,FN_LOG,512><<<BATCH, 512>>>(S->bufA, S->logmb, nullptr, 1, BIG, 1, 0);
    mean_kernel<<<dim3(40, 1), 256>>>(S->logmb, S->meanb, BATCH, 1, 10000);
    eigh1s_kernel<100,FN_EXPNEGHALF,512><<<1, 512>>>(S->meanb, S->gib, nullptr, 1, BIG, 1, 0);
    bimap_kernel<100,100><<<BATCH, 512, B100>>>(S->gib, S->gib, BIG, S->bufA, S->s, 1, 1, 0);

    // 3) reeig(s), shared by both pre branches
    eigh1s_kernel<100,FN_REEIG,512><<<BATCH, 512>>>(S->s, S->reeig, nullptr, 1, BIG, 1, 0);

    // 4) merged pre0+pre1 chain: 4 channels [pre0c0, pre0c1, pre1c0, pre1c1]
    bimap_kernel<100,100><<<4*BATCH, 512, B100>>>(pre0_w, pre1_w, 2, S->reeig, S->bufA01, 1, 4, 0);
    eigh1s_kernel<100,FN_LOG,512><<<4*BATCH, 512>>>(S->bufA01, S->logmb, nullptr, 1, BIG, 1, 0);
    mean_kernel<<<dim3(40, 4), 256>>>(S->logmb, S->meanb, BATCH, 4, 10000);
    eigh1s_kernel<100,FN_EXPNEGHALF,512><<<4, 512>>>(S->meanb, S->gib, nullptr, 1, BIG, 1, 0);
    bimap_kernel<100,100><<<4*BATCH, 512, B100>>>(S->gib, S->gib, BIG, S->bufA01, S->s01, 4, 4, 0);

    // 5) reduce to 50x50: s0 = channels 0,1 of s01; s1 = channels 2,3
    bimap_kernel<100,50><<<2*BATCH, 512, B10050>>>(wr0, wr0, BIG, S->s01, S->bimA, 4, 2, 0);
    bimap_kernel<100,50><<<2*BATCH, 512, B10050>>>(wr1, wr1, BIG, S->s01 + 2 * N100 * N100, S->bimB, 4, 2, 0);

    // bary2: dst = sym( sqrt(A) * sqrt( sym(invsqrt(A)*Bm*invsqrt(A)) ) * sqrt(A) )
    auto bary2 = [&](const float* A, const float* Bm, float* dst) {
        eigh1s_kernel<50,FN_SQRT_BOTH,512><<<2*BATCH, 512>>>(A, S->As, S->Ais, 1, BIG, 1, 0);
        bimap_kernel<50,50><<<2*BATCH, 512, B50>>>(S->Ais, S->Ais, BIG, Bm, S->Mmid, 2, 2, 1);
        eigh1s_kernel<50,FN_SQRT,512><<<2*BATCH, 512>>>(S->Mmid, S->Ssq, nullptr, 1, BIG, 1, 0);
        bimap_kernel<50,50><<<2*BATCH, 512, B50>>>(S->As, S->As, BIG, S->Ssq, dst, 2, 2, 1);
    };

    // 6) states
    bary2(S->bimA, S->bimB, S->st2);
    bimap_kernel<50,50><<<2*BATCH, 512, B50>>>(wn2, wn2, BIG, S->st2, S->bimA, 2, 2, 0);
    bary2(S->bimA, S->st2, S->st3);
    bimap_kernel<50,50><<<2*BATCH, 512, B50>>>(wn4, wn4, BIG, S->st3, S->bimA, 2, 2, 0);
    bary2(S->bimA, S->st2, S->st4);
    bimap_kernel<50,50><<<2*BATCH, 512, B50>>>(wn7, wn7, BIG, S->st3, S->bimB, 2, 2, 0);
    bary2(S->st4, S->bimB, S->st5);

    // 7) merged logm of st2..st5 (contiguous) into feat (B, 8, 50, 50)
    //    m = stage*128 + b*2 + c  ->  ooff = (b*8 + stage*2 + c) * 2500
    eigh1s_kernel<50,FN_LOG,512><<<8*BATCH, 512>>>(S->st2, S->feat, nullptr, 2, BATCH, 8, 2);

    // 8) classifier
    cls_gemm_kernel<<<125, 256>>>(S->feat, cls_w, S->clsPart);
    cls_reduce_kernel<<<25, 256>>>(S->clsPart, cls_b, out, 125);
}